// round 6
// baseline (speedup 1.0000x reference)
#include <cuda_runtime.h>

#define NB     11
#define NBINS  1331        // 11^3
#define ITER   20
#define TPB    32          // one warp per block
#define NGC    8           // global histogram copies
#define CHUNK  56          // u8 flush period: max +4/iter/copy -> 224 <= 255

__device__ int          g_histG[NGC][NBINS];  // zero-init; re-zeroed by last block
__device__ unsigned int g_done;               // zero-init; reset by last block

__global__ void __launch_bounds__(TPB) fused_kernel(
    const float4* __restrict__ x, int n, int full, int stride,
    const float*  __restrict__ r_cut,
    const float*  __restrict__ g_cut,
    const float*  __restrict__ b_cut,
    float* __restrict__ out)
{
    // per-warp u8 histogram: 8 copies; lanes {l, l+8, l+16, l+24} share copy lane&7
    __shared__ __align__(16) unsigned char wh[NBINS * 8];     // 10648 B
    __shared__ unsigned char s_lut[3 * 256];                  // 768 B exact-LUT
    __shared__ float s_cut255[3][NB];
    __shared__ float s_cut01[3][NB];
    __shared__ int s_top[ITER];
    __shared__ int s_last;

    const int lane = threadIdx.x;

    // ---- cuts: clip + rank-sort (clip/sort commute; stable ties by index) ----
    for (int item = lane; item < 33; item += TPB) {
        int c = item / NB, j = item - c * NB;
        const float* src = (c == 0) ? r_cut : (c == 1) ? g_cut : b_cut;
        float vj = fminf(fmaxf(src[j], 0.0f), 1.0f);
        int rank = 0;
        for (int k = 0; k < NB; k++) {
            float vk = fminf(fmaxf(src[k], 0.0f), 1.0f);
            rank += (vk < vj) || (vk == vj && k < j);
        }
        s_cut01[c][rank] = vj;
    }
    {   // zero private histogram (1331 × 8B)
        uint2* w2 = (uint2*)wh;
        for (int i = lane; i < NBINS; i += TPB) w2[i] = make_uint2(0u, 0u);
    }
    __syncwarp();
    for (int item = lane; item < 33; item += TPB) {
        int c = item / NB, j = item - c * NB;
        float v = s_cut01[c][j];
        if (j == 0)      v = 0.0f;
        if (j == NB - 1) v = 1.0f;
        s_cut01[c][j]  = v;
        s_cut255[c][j] = v * 255.0f;
    }
    __syncwarp();

    // ---- exact searchsorted LUT. For k = floor(x):
    //   iv = #{cut < k}  +  (rare) exact compares of cuts in [k, k+1).
    // cut[10] = 255 > x always (x = u*255, u<1 -> x<255 in fp32) -> only j=0..9.
    for (int i = lane; i < 3 * 256; i += TPB) {
        int c = i >> 8, k = i & 255;
        float fk = (float)k, fk1 = (float)(k + 1);
        int base = 0, hasB = 0;
        for (int j = 0; j < NB - 1; j++) {
            float cv = s_cut255[c][j];
            base += (cv < fk);
            hasB |= (cv >= fk) && (cv < fk1);
        }
        s_lut[i] = (unsigned char)(base | (hasB << 7));
    }
    __syncwarp();

    const int copy = lane & 7;
    const int q    = lane >> 3;
    const int gtid = blockIdx.x * TPB + lane;
    int* gdst = g_histG[blockIdx.x & (NGC - 1)];

    // searchsorted via LUT + rare exact boundary compares
#define BIN_OF(p, bin) do {                                                    \
        int _kr = __float2int_rd((p).x);                                       \
        int _kg = __float2int_rd((p).y);                                       \
        int _kb = __float2int_rd((p).z);                                       \
        unsigned _er = s_lut[_kr];                                             \
        unsigned _eg = s_lut[256 + _kg];                                       \
        unsigned _eb = s_lut[512 + _kb];                                       \
        int ri = _er & 15, gi = _eg & 15, bi = _eb & 15;                       \
        if (_er & 128) { int _j = ri;                                          \
            for (; _j < NB - 1; _j++) ri += (s_cut255[0][_j] < (p).x); }       \
        if (_eg & 128) { int _j = gi;                                          \
            for (; _j < NB - 1; _j++) gi += (s_cut255[1][_j] < (p).y); }       \
        if (_eb & 128) { int _j = bi;                                          \
            for (; _j < NB - 1; _j++) bi += (s_cut255[2][_j] < (p).z); }       \
        ri -= 1; if (ri < 0) ri += NB;   /* (iv-1) mod 11 */                   \
        gi -= 1; if (gi < 0) gi += NB;                                         \
        bi -= 1; if (bi < 0) bi += NB;                                         \
        (bin) = (ri * NB + gi) * NB + bi;                                      \
    } while (0)

    // 4-lane-group dedup (3 shuffles), exactly one leader per matching set
#define DEPOSIT(bin, valid) do {                                               \
        int _b   = (bin);                                                      \
        int _b8  = __shfl_xor_sync(0xffffffffu, _b, 8);                        \
        int _b16 = __shfl_xor_sync(0xffffffffu, _b, 16);                       \
        int _b24 = __shfl_xor_sync(0xffffffffu, _b, 24);                       \
        int _e8  = (_b == _b8), _e16 = (_b == _b16), _e24 = (_b == _b24);      \
        int _add = 1 + _e8 + _e16 + _e24;                                      \
        bool _ldr = !((_e8 && (q & 1)) || (_e16 && (q & 2)) || (_e24 && (q & 2))); \
        if ((valid) && _ldr) {                                                 \
            unsigned char* _p = wh + _b * 8 + copy;                            \
            *_p = (unsigned char)(*_p + _add);                                 \
        }                                                                      \
    } while (0)

#define FLUSH() do {                                                           \
        __syncwarp();                                                          \
        for (int _bin = lane; _bin < NBINS; _bin += TPB) {                     \
            uint2* _wp = (uint2*)(wh + _bin * 8);                              \
            uint2 _w = *_wp;                                                   \
            unsigned _s = __dp4a(_w.x, 0x01010101u,                            \
                          __dp4a(_w.y, 0x01010101u, 0u));                      \
            *_wp = make_uint2(0u, 0u);                                         \
            if (_s) atomicAdd(&gdst[_bin], (int)_s);                           \
        }                                                                      \
        __syncwarp();                                                          \
    } while (0)

    // ---- main loop: CHUNK iterations per flush, unroll-8 batched loads ----
    int r = 0;
    while (r < full) {
        int end = min(r + CHUNK, full);
#pragma unroll 8
        for (; r < end; r++) {
            float4 p = __ldcs(&x[gtid + r * stride]);
            int bin;
            BIN_OF(p, bin);
            DEPOSIT(bin, true);
        }
        FLUSH();
    }
    // guarded tail round
    {
        int idx = gtid + full * stride;
        bool valid = idx < n;
        int bin = -1 - lane;            // unique per lane -> no false match
        if (valid) {
            float4 p = __ldcs(&x[idx]);
            BIN_OF(p, bin);
        }
        DEPOSIT(bin, valid);
        FLUSH();
    }

    // ---- ticket: last block does the top-k ----
    __threadfence();
    if (lane == 0) s_last = (atomicAdd(&g_done, 1u) == (unsigned)gridDim.x - 1u);
    __syncwarp();
    if (!s_last) return;
    __threadfence();

    unsigned long long* keys = (unsigned long long*)wh;   // 1331*8 B, exact fit
    for (int i = lane; i < NBINS; i += TPB) {
        unsigned int c = 0;
#pragma unroll
        for (int k = 0; k < NGC; k++) c += (unsigned int)__ldcg(&g_histG[k][i]);
        keys[i] = (((unsigned long long)c << 11) |
                   (unsigned long long)(1330 - i)) + 1ull;
#pragma unroll
        for (int k = 0; k < NGC; k++) g_histG[k][i] = 0;   // reset for replay
    }
    __syncwarp();

    for (int it = 0; it < ITER; it++) {
        unsigned long long m = 0;
        for (int i = lane; i < NBINS; i += TPB) {
            unsigned long long k = keys[i];
            m = (k > m) ? k : m;
        }
#pragma unroll
        for (int o = 16; o > 0; o >>= 1) {
            unsigned long long k = __shfl_xor_sync(0xffffffffu, m, o);
            m = (k > m) ? k : m;
        }
        m = __shfl_sync(0xffffffffu, m, 0);
        int bin = 1330 - (int)((m - 1ull) & 0x7FFull);
        if (lane == 0) {
            s_top[it] = bin;
            keys[bin] = 0ull;
        }
        __syncwarp();
    }

    if (lane < ITER) {
        int bin = s_top[lane];
        int r2 = bin / 121;
        int g2 = (bin / 11) % 11;
        int b2 = bin % 11;
        r2 = min(r2, NB - 2);
        g2 = min(g2, NB - 2);
        b2 = min(b2, NB - 2);
        float rv = 255.0f * (float)r2 / (float)NB + (s_cut01[0][r2 + 1] - s_cut01[0][r2]) * 255.0f / 2.0f;
        float gv = 255.0f * (float)g2 / (float)NB + (s_cut01[1][g2 + 1] - s_cut01[1][g2]) * 255.0f / 2.0f;
        float bv = 255.0f * (float)b2 / (float)NB + (s_cut01[2][b2 + 1] - s_cut01[2][b2]) * 255.0f / 2.0f;
        out[lane * 4 + 0] = rv;
        out[lane * 4 + 1] = gv;
        out[lane * 4 + 2] = bv;
        out[lane * 4 + 3] = 255.0f;
    }
    if (lane == 0) g_done = 0;   // reset ticket for next replay
}

// ---------------------------------------------------------------------------
extern "C" void kernel_launch(void* const* d_in, const int* in_sizes, int n_in,
                              void* d_out, int out_size) {
    const float* x  = (const float*)d_in[0];
    const float* rc = (const float*)d_in[1];
    const float* gc = (const float*)d_in[2];
    const float* bc = (const float*)d_in[3];
    int n = in_sizes[0] / 4;   // number of pixels

    // size grid to exactly one resident wave (host-side, capture-safe)
    int dev = 0, sms = 148, occ = 10;
    cudaGetDevice(&dev);
    cudaDeviceGetAttribute(&sms, cudaDevAttrMultiProcessorCount, dev);
    cudaOccupancyMaxActiveBlocksPerMultiprocessor(&occ, fused_kernel, TPB, 0);
    if (occ < 1) occ = 1;
    int grid   = sms * occ;
    int stride = grid * TPB;
    int full   = n / stride;

    fused_kernel<<<grid, TPB>>>((const float4*)x, n, full, stride,
                                rc, gc, bc, (float*)d_out);
}

// round 7
// speedup vs baseline: 2.8478x; 2.8478x over previous
#include <cuda_runtime.h>

#define NB     11
#define NBINS  1331        // 11^3
#define ITER   20
#define TPB    128         // 4 warps per block
#define NWARP  4
#define WHB    (NBINS * 8) // bytes per warp-private histogram (u8, 8 copies)
#define NGC    8           // global histogram copies
#define CHUNK  63          // u8 flush period: max +4/iter/copy -> 252 <= 255

__device__ int          g_histG[NGC][NBINS];  // zero-init; re-zeroed by last block
__device__ unsigned int g_done;               // zero-init; reset by last block

__global__ void __launch_bounds__(TPB) fused_kernel(
    const float4* __restrict__ x, int n, int full, int stride,
    const float*  __restrict__ r_cut,
    const float*  __restrict__ g_cut,
    const float*  __restrict__ b_cut,
    float* __restrict__ out)
{
    // 4 warp-private u8 histograms, 8 copies each; lanes {l,l+8,l+16,l+24}
    // share copy (lane&7) inside their warp's region.
    __shared__ __align__(16) unsigned char wh[NWARP * WHB];   // 42592 B
    __shared__ float s_cut255[3][NB];
    __shared__ float s_cut01[3][NB];
    __shared__ unsigned long long s_wmax[NWARP];
    __shared__ int s_top[ITER];
    __shared__ int s_last;

    const int tid  = threadIdx.x;
    const int lane = tid & 31;
    const int wid  = tid >> 5;

    // ---- cuts: clip + rank-sort (clip/sort commute; stable ties by index) ----
    if (tid < 33) {
        int c = tid / NB, j = tid - c * NB;
        const float* src = (c == 0) ? r_cut : (c == 1) ? g_cut : b_cut;
        float vj = fminf(fmaxf(src[j], 0.0f), 1.0f);
        int rank = 0;
        for (int k = 0; k < NB; k++) {
            float vk = fminf(fmaxf(src[k], 0.0f), 1.0f);
            rank += (vk < vj) || (vk == vj && k < j);
        }
        s_cut01[c][rank] = vj;
    }
    {   // zero private histograms
        uint4* w4 = (uint4*)wh;
        for (int i = tid; i < (NWARP * WHB) / 16; i += TPB) w4[i] = make_uint4(0u, 0u, 0u, 0u);
    }
    __syncthreads();
    if (tid < 33) {
        int c = tid / NB, j = tid - c * NB;
        float v = s_cut01[c][j];
        if (j == 0)      v = 0.0f;
        if (j == NB - 1) v = 1.0f;
        s_cut01[c][j]  = v;
        s_cut255[c][j] = v * 255.0f;
    }
    __syncthreads();

    // cut[10]*255 == 255 and x = u*255 with u<1 -> x < 255 always in fp32,
    // so the j==10 compare is always false: 10 compares per channel.
    float rc[NB - 1], gc[NB - 1], bc[NB - 1];
#pragma unroll
    for (int i = 0; i < NB - 1; i++) {
        rc[i] = s_cut255[0][i];
        gc[i] = s_cut255[1][i];
        bc[i] = s_cut255[2][i];
    }

    unsigned char* __restrict__ myh = wh + wid * WHB;
    const int copy = lane & 7;
    const int q    = lane >> 3;
    const int gtid = blockIdx.x * TPB + tid;
    int* gdst = g_histG[blockIdx.x & (NGC - 1)];

    // branchless searchsorted: 10 compares per channel (proven R5 path)
#define BIN_OF(p, bin) do {                                                    \
        int ri = 0, gi = 0, bi = 0;                                            \
        _Pragma("unroll")                                                      \
        for (int j = 0; j < NB - 1; j++) {                                     \
            ri += (rc[j] < (p).x);                                             \
            gi += (gc[j] < (p).y);                                             \
            bi += (bc[j] < (p).z);                                             \
        }                                                                      \
        ri -= 1; if (ri < 0) ri += NB;   /* (iv-1) mod 11 */                   \
        gi -= 1; if (gi < 0) gi += NB;                                         \
        bi -= 1; if (bi < 0) bi += NB;                                         \
        (bin) = (ri * NB + gi) * NB + bi;                                      \
    } while (0)

    // 4-lane-group dedup (3 independent shuffles), exactly one leader per set
#define DEPOSIT(bin, valid) do {                                               \
        int _b   = (bin);                                                      \
        int _b8  = __shfl_xor_sync(0xffffffffu, _b, 8);                        \
        int _b16 = __shfl_xor_sync(0xffffffffu, _b, 16);                       \
        int _b24 = __shfl_xor_sync(0xffffffffu, _b, 24);                       \
        int _e8  = (_b == _b8), _e16 = (_b == _b16), _e24 = (_b == _b24);      \
        int _add = 1 + _e8 + _e16 + _e24;                                      \
        bool _ldr = !((_e8 && (q & 1)) || (_e16 && (q & 2)) || (_e24 && (q & 2))); \
        if ((valid) && _ldr) {                                                 \
            unsigned char* _p = myh + _b * 8 + copy;                           \
            *_p = (unsigned char)(*_p + _add);                                 \
        }                                                                      \
    } while (0)

    // block-level flush: merge all 4 warp hists per bin (dp4a), one ATOMG per
    // bin per block per pass; zero in place.
#define FLUSH() do {                                                           \
        __syncthreads();                                                       \
        for (int _bin = tid; _bin < NBINS; _bin += TPB) {                      \
            unsigned _s = 0;                                                   \
            _Pragma("unroll")                                                  \
            for (int _w = 0; _w < NWARP; _w++) {                               \
                uint2* _wp = (uint2*)(wh + _w * WHB + _bin * 8);               \
                uint2 _v = *_wp;                                               \
                *_wp = make_uint2(0u, 0u);                                     \
                _s = __dp4a(_v.x, 0x01010101u,                                 \
                     __dp4a(_v.y, 0x01010101u, _s));                           \
            }                                                                  \
            if (_s) atomicAdd(&gdst[_bin], (int)_s);                           \
        }                                                                      \
        __syncthreads();                                                       \
    } while (0)

    // ---- main loop: CHUNK iterations per flush, unroll-8 batched loads ----
    int r = 0;
    while (r < full) {
        int end = min(r + CHUNK, full);
#pragma unroll 8
        for (; r < end; r++) {
            float4 p = __ldcs(&x[gtid + r * stride]);
            int bin;
            BIN_OF(p, bin);
            DEPOSIT(bin, true);
        }
        FLUSH();
    }
    // guarded tail round (hist freshly zeroed; adds <= 4 per copy)
    {
        int idx = gtid + full * stride;
        bool valid = idx < n;
        int bin = -1 - lane;            // unique per lane -> no false match
        if (valid) {
            float4 p = __ldcs(&x[idx]);
            BIN_OF(p, bin);
        }
        DEPOSIT(bin, valid);
        FLUSH();
    }

    // ---- ticket: last block does the top-k ----
    __threadfence();
    if (tid == 0) s_last = (atomicAdd(&g_done, 1u) == (unsigned)gridDim.x - 1u);
    __syncthreads();
    if (!s_last) return;
    __threadfence();

    unsigned long long* keys = (unsigned long long*)wh;   // 10648 B, fits
    for (int i = tid; i < NBINS; i += TPB) {
        unsigned int c = 0;
#pragma unroll
        for (int k = 0; k < NGC; k++) c += (unsigned int)__ldcg(&g_histG[k][i]);
        keys[i] = (((unsigned long long)c << 11) |
                   (unsigned long long)(1330 - i)) + 1ull;
#pragma unroll
        for (int k = 0; k < NGC; k++) g_histG[k][i] = 0;   // reset for replay
    }
    __syncthreads();

    for (int it = 0; it < ITER; it++) {
        unsigned long long m = 0;
        for (int i = tid; i < NBINS; i += TPB) {
            unsigned long long k = keys[i];
            m = (k > m) ? k : m;
        }
#pragma unroll
        for (int o = 16; o > 0; o >>= 1) {
            unsigned long long k = __shfl_xor_sync(0xffffffffu, m, o);
            m = (k > m) ? k : m;
        }
        if (lane == 0) s_wmax[wid] = m;
        __syncthreads();
        if (tid == 0) {
            unsigned long long w = 0;
#pragma unroll
            for (int k = 0; k < NWARP; k++) w = (s_wmax[k] > w) ? s_wmax[k] : w;
            int bin = 1330 - (int)((w - 1ull) & 0x7FFull);
            s_top[it] = bin;
            keys[bin] = 0ull;
        }
        __syncthreads();
    }

    if (tid < ITER) {
        int bin = s_top[tid];
        int r2 = bin / 121;
        int g2 = (bin / 11) % 11;
        int b2 = bin % 11;
        r2 = min(r2, NB - 2);
        g2 = min(g2, NB - 2);
        b2 = min(b2, NB - 2);
        float rv = 255.0f * (float)r2 / (float)NB + (s_cut01[0][r2 + 1] - s_cut01[0][r2]) * 255.0f / 2.0f;
        float gv = 255.0f * (float)g2 / (float)NB + (s_cut01[1][g2 + 1] - s_cut01[1][g2]) * 255.0f / 2.0f;
        float bv = 255.0f * (float)b2 / (float)NB + (s_cut01[2][b2 + 1] - s_cut01[2][b2]) * 255.0f / 2.0f;
        out[tid * 4 + 0] = rv;
        out[tid * 4 + 1] = gv;
        out[tid * 4 + 2] = bv;
        out[tid * 4 + 3] = 255.0f;
    }
    if (tid == 0) g_done = 0;   // reset ticket for next replay
}

// ---------------------------------------------------------------------------
extern "C" void kernel_launch(void* const* d_in, const int* in_sizes, int n_in,
                              void* d_out, int out_size) {
    const float* x  = (const float*)d_in[0];
    const float* rc = (const float*)d_in[1];
    const float* gc = (const float*)d_in[2];
    const float* bc = (const float*)d_in[3];
    int n = in_sizes[0] / 4;   // number of pixels

    // size grid to exactly one resident wave (host-side, capture-safe)
    int dev = 0, sms = 148, occ = 5;
    cudaGetDevice(&dev);
    cudaDeviceGetAttribute(&sms, cudaDevAttrMultiProcessorCount, dev);
    cudaOccupancyMaxActiveBlocksPerMultiprocessor(&occ, fused_kernel, TPB, 0);
    if (occ < 1) occ = 1;
    int grid   = sms * occ;
    int stride = grid * TPB;
    int full   = n / stride;

    fused_kernel<<<grid, TPB>>>((const float4*)x, n, full, stride,
                                rc, gc, bc, (float*)d_out);
}

// round 8
// speedup vs baseline: 3.4216x; 1.2015x over previous
#include <cuda_runtime.h>

#define NB     11
#define NBINS  1331        // 11^3
#define ITER   20
#define TPB    128         // 4 warps per block
#define NWARP  4
#define WHB    (NBINS * 8) // bytes per warp-private histogram (u8, 8 copies)
#define NGC    8           // global histogram copies
#define CHUNK  63          // u8 flush period: max +4/iter/copy -> 252 <= 255

__device__ int          g_histG[NGC][NBINS];  // zero-init; re-zeroed by last block
__device__ unsigned int g_done;               // zero-init; reset by last block

// Predicated compare-accumulate, exact searchsorted weights folded in:
//   acc = selp(x>c0, W, 11W) + sum_{j=1..9} W*(x > c_j)
// (bin contribution = W*((iv-1) mod 11) = acc - W; the -W is folded into -133.)
#define CHAN_ACC(acc, xx, c, WS, W11S)                                         \
    asm("{\n\t"                                                                \
        ".reg .pred p;\n\t"                                                    \
        "setp.gt.f32 p, %1, %2;\n\t"                                           \
        "selp.b32 %0, " WS ", " W11S ", p;\n\t"                                \
        "setp.gt.f32 p, %1, %3;\n\t@p add.s32 %0, %0, " WS ";\n\t"             \
        "setp.gt.f32 p, %1, %4;\n\t@p add.s32 %0, %0, " WS ";\n\t"             \
        "setp.gt.f32 p, %1, %5;\n\t@p add.s32 %0, %0, " WS ";\n\t"             \
        "setp.gt.f32 p, %1, %6;\n\t@p add.s32 %0, %0, " WS ";\n\t"             \
        "setp.gt.f32 p, %1, %7;\n\t@p add.s32 %0, %0, " WS ";\n\t"             \
        "setp.gt.f32 p, %1, %8;\n\t@p add.s32 %0, %0, " WS ";\n\t"             \
        "setp.gt.f32 p, %1, %9;\n\t@p add.s32 %0, %0, " WS ";\n\t"             \
        "setp.gt.f32 p, %1, %10;\n\t@p add.s32 %0, %0, " WS ";\n\t"            \
        "setp.gt.f32 p, %1, %11;\n\t@p add.s32 %0, %0, " WS ";\n\t"            \
        "}"                                                                    \
        : "=r"(acc)                                                            \
        : "f"(xx), "f"((c)[0]), "f"((c)[1]), "f"((c)[2]), "f"((c)[3]),         \
          "f"((c)[4]), "f"((c)[5]), "f"((c)[6]), "f"((c)[7]), "f"((c)[8]),     \
          "f"((c)[9]))

// Deposit with vote fast-path: collisions within 4-lane copy-groups are rare
// (~3.6%/warp-iter); fast path is a bare u8 RMW of +1.
template <bool GUARDED>
__device__ __forceinline__ void deposit(unsigned char* __restrict__ myhc,
                                        int bin, int q, bool valid) {
    int b8  = __shfl_xor_sync(0xffffffffu, bin, 8);
    int b16 = __shfl_xor_sync(0xffffffffu, bin, 16);
    int b24 = __shfl_xor_sync(0xffffffffu, bin, 24);
    bool col = (bin == b8) || (bin == b16) || (bin == b24);
    if (!__any_sync(0xffffffffu, col)) {
        if (!GUARDED || valid) {
            unsigned char* p = myhc + (bin << 3);
            *p = (unsigned char)(*p + 1);
        }
    } else {
        int e8 = (bin == b8), e16 = (bin == b16), e24 = (bin == b24);
        int add = 1 + e8 + e16 + e24;
        bool ldr = !((e8 && (q & 1)) || ((e16 || e24) && (q & 2)));
        if ((!GUARDED || valid) && ldr) {
            unsigned char* p = myhc + (bin << 3);
            *p = (unsigned char)(*p + add);
        }
    }
}

__global__ void __launch_bounds__(TPB, 5) fused_kernel(
    const float4* __restrict__ x, int n, int full, int stride,
    const float*  __restrict__ r_cut,
    const float*  __restrict__ g_cut,
    const float*  __restrict__ b_cut,
    float* __restrict__ out)
{
    __shared__ __align__(16) unsigned char wh[NWARP * WHB];   // 42592 B
    __shared__ float s_cut255[3][NB];
    __shared__ float s_cut01[3][NB];
    __shared__ unsigned long long s_wmax[NWARP];
    __shared__ int s_top[ITER];
    __shared__ int s_last;

    const int tid  = threadIdx.x;
    const int lane = tid & 31;
    const int wid  = tid >> 5;

    // ---- cuts: clip + rank-sort (clip/sort commute; stable ties by index) ----
    if (tid < 33) {
        int c = tid / NB, j = tid - c * NB;
        const float* src = (c == 0) ? r_cut : (c == 1) ? g_cut : b_cut;
        float vj = fminf(fmaxf(src[j], 0.0f), 1.0f);
        int rank = 0;
        for (int k = 0; k < NB; k++) {
            float vk = fminf(fmaxf(src[k], 0.0f), 1.0f);
            rank += (vk < vj) || (vk == vj && k < j);
        }
        s_cut01[c][rank] = vj;
    }
    {   // zero private histograms
        uint4* w4 = (uint4*)wh;
        for (int i = tid; i < (NWARP * WHB) / 16; i += TPB) w4[i] = make_uint4(0u, 0u, 0u, 0u);
    }
    __syncthreads();
    if (tid < 33) {
        int c = tid / NB, j = tid - c * NB;
        float v = s_cut01[c][j];
        if (j == 0)      v = 0.0f;
        if (j == NB - 1) v = 1.0f;
        s_cut01[c][j]  = v;
        s_cut255[c][j] = v * 255.0f;
    }
    __syncthreads();

    // cut[10]*255 == 255 > x always (x = u*255, u<1) -> only j=0..9 compare.
    float rc[NB - 1], gc[NB - 1], bc[NB - 1];
#pragma unroll
    for (int i = 0; i < NB - 1; i++) {
        rc[i] = s_cut255[0][i];
        gc[i] = s_cut255[1][i];
        bc[i] = s_cut255[2][i];
    }

    const int copy = lane & 7;
    const int q    = lane >> 3;
    unsigned char* __restrict__ myhc = wh + wid * WHB + copy;  // + bin*8 in deposit
    const int gtid = blockIdx.x * TPB + tid;
    int* gdst = g_histG[blockIdx.x & (NGC - 1)];

#define BIN_OF(p, bin) do {                                                    \
        int accR, accG, accB;                                                  \
        CHAN_ACC(accR, (p).x, rc, "121", "1331");                              \
        CHAN_ACC(accG, (p).y, gc, "11",  "121");                               \
        CHAN_ACC(accB, (p).z, bc, "1",   "11");                                \
        (bin) = accR + accG + accB - 133;                                      \
    } while (0)

    // block-level flush: merge all 4 warp hists per bin (dp4a), one ATOMG per
    // bin per block per pass; zero in place.
#define FLUSH() do {                                                           \
        __syncthreads();                                                       \
        for (int _bin = tid; _bin < NBINS; _bin += TPB) {                      \
            unsigned _s = 0;                                                   \
            _Pragma("unroll")                                                  \
            for (int _w = 0; _w < NWARP; _w++) {                               \
                uint2* _wp = (uint2*)(wh + _w * WHB + _bin * 8);               \
                uint2 _v = *_wp;                                               \
                *_wp = make_uint2(0u, 0u);                                     \
                _s = __dp4a(_v.x, 0x01010101u,                                 \
                     __dp4a(_v.y, 0x01010101u, _s));                           \
            }                                                                  \
            if (_s) atomicAdd(&gdst[_bin], (int)_s);                           \
        }                                                                      \
        __syncthreads();                                                       \
    } while (0)

    // ---- main loop: CHUNK iterations per flush, unroll-8 batched loads ----
    int r = 0;
    while (r < full) {
        int end = min(r + CHUNK, full);
#pragma unroll 8
        for (; r < end; r++) {
            float4 p = __ldcs(&x[gtid + r * stride]);
            int bin;
            BIN_OF(p, bin);
            deposit<false>(myhc, bin, q, true);
        }
        FLUSH();
    }
    // guarded tail round (hist freshly zeroed; adds <= 4 per copy)
    {
        int idx = gtid + full * stride;
        bool valid = idx < n;
        int bin = -1 - lane;            // unique per lane -> no false match
        if (valid) {
            float4 p = __ldcs(&x[idx]);
            BIN_OF(p, bin);
        }
        deposit<true>(myhc, bin, q, valid);
        FLUSH();
    }

    // ---- ticket: last block does the top-k ----
    __threadfence();
    if (tid == 0) s_last = (atomicAdd(&g_done, 1u) == (unsigned)gridDim.x - 1u);
    __syncthreads();
    if (!s_last) return;
    __threadfence();

    unsigned long long* keys = (unsigned long long*)wh;   // 10648 B, fits
    for (int i = tid; i < NBINS; i += TPB) {
        unsigned int c = 0;
#pragma unroll
        for (int k = 0; k < NGC; k++) c += (unsigned int)__ldcg(&g_histG[k][i]);
        keys[i] = (((unsigned long long)c << 11) |
                   (unsigned long long)(1330 - i)) + 1ull;
#pragma unroll
        for (int k = 0; k < NGC; k++) g_histG[k][i] = 0;   // reset for replay
    }
    __syncthreads();

    for (int it = 0; it < ITER; it++) {
        unsigned long long m = 0;
        for (int i = tid; i < NBINS; i += TPB) {
            unsigned long long k = keys[i];
            m = (k > m) ? k : m;
        }
#pragma unroll
        for (int o = 16; o > 0; o >>= 1) {
            unsigned long long k = __shfl_xor_sync(0xffffffffu, m, o);
            m = (k > m) ? k : m;
        }
        if (lane == 0) s_wmax[wid] = m;
        __syncthreads();
        if (tid == 0) {
            unsigned long long w = 0;
#pragma unroll
            for (int k = 0; k < NWARP; k++) w = (s_wmax[k] > w) ? s_wmax[k] : w;
            int bin = 1330 - (int)((w - 1ull) & 0x7FFull);
            s_top[it] = bin;
            keys[bin] = 0ull;
        }
        __syncthreads();
    }

    if (tid < ITER) {
        int bin = s_top[tid];
        int r2 = bin / 121;
        int g2 = (bin / 11) % 11;
        int b2 = bin % 11;
        r2 = min(r2, NB - 2);
        g2 = min(g2, NB - 2);
        b2 = min(b2, NB - 2);
        float rv = 255.0f * (float)r2 / (float)NB + (s_cut01[0][r2 + 1] - s_cut01[0][r2]) * 255.0f / 2.0f;
        float gv = 255.0f * (float)g2 / (float)NB + (s_cut01[1][g2 + 1] - s_cut01[1][g2]) * 255.0f / 2.0f;
        float bv = 255.0f * (float)b2 / (float)NB + (s_cut01[2][b2 + 1] - s_cut01[2][b2]) * 255.0f / 2.0f;
        out[tid * 4 + 0] = rv;
        out[tid * 4 + 1] = gv;
        out[tid * 4 + 2] = bv;
        out[tid * 4 + 3] = 255.0f;
    }
    if (tid == 0) g_done = 0;   // reset ticket for next replay
}

// ---------------------------------------------------------------------------
extern "C" void kernel_launch(void* const* d_in, const int* in_sizes, int n_in,
                              void* d_out, int out_size) {
    const float* x  = (const float*)d_in[0];
    const float* rc = (const float*)d_in[1];
    const float* gc = (const float*)d_in[2];
    const float* bc = (const float*)d_in[3];
    int n = in_sizes[0] / 4;   // number of pixels

    // size grid to exactly one resident wave (host-side, capture-safe)
    int dev = 0, sms = 148, occ = 5;
    cudaGetDevice(&dev);
    cudaDeviceGetAttribute(&sms, cudaDevAttrMultiProcessorCount, dev);
    cudaOccupancyMaxActiveBlocksPerMultiprocessor(&occ, fused_kernel, TPB, 0);
    if (occ < 1) occ = 1;
    int grid   = sms * occ;
    int stride = grid * TPB;
    int full   = n / stride;

    fused_kernel<<<grid, TPB>>>((const float4*)x, n, full, stride,
                                rc, gc, bc, (float*)d_out);
}